// round 1
// baseline (speedup 1.0000x reference)
#include <cuda_runtime.h>
#include <cstdint>

#define FULLM 0xffffffffu
#define DINLINE __device__ __forceinline__

constexpr int NN = 150000, CC = 256, LL = 50000, KTOP = 200;
constexpr int NU = NN - LL;           // 100000 unlabeled rows
constexpr int SEGL2 = 1352;           // 74 * 1352 = 100048 >= NU

// ---------------- scratch (device globals; no allocation allowed) ------------
__device__ float g_prob[(size_t)NU * CC];   // prob / p for unlabeled rows (102.4 MB)
__device__ int   g_cls[NN];
__device__ float g_rnorm[NN];
__device__ float g_psum[CC * CC];
__device__ float g_protos[CC * CC];
__device__ float g_protoN[CC * CC];
__device__ float g_S[CC * CC];
__device__ float g_colsum[CC];
__device__ int   g_cntall[CC];
__device__ int   g_cntlab[CC];

// ---------------- helpers ----------------------------------------------------
DINLINE unsigned long long ffma2(unsigned long long a, unsigned long long b,
                                 unsigned long long c) {
    unsigned long long d;
    asm("fma.rn.f32x2 %0, %1, %2, %3;" : "=l"(d) : "l"(a), "l"(b), "l"(c));
    return d;
}
DINLINE unsigned long long bcast2(float f) {
    unsigned long long d; unsigned u = __float_as_uint(f);
    asm("mov.b64 %0, {%1, %1};" : "=l"(d) : "r"(u));
    return d;
}
DINLINE float2 unpk(unsigned long long u) {
    return make_float2(__uint_as_float((unsigned)(u & 0xffffffffull)),
                       __uint_as_float((unsigned)(u >> 32)));
}
DINLINE float block_reduce_sum(float v) {
    __shared__ float red[8];
    __shared__ float tot;
    for (int o = 16; o; o >>= 1) v += __shfl_xor_sync(FULLM, v, o);
    if ((threadIdx.x & 31) == 0) red[threadIdx.x >> 5] = v;
    __syncthreads();
    if (threadIdx.x < 32) {
        float s = (threadIdx.x < 8) ? red[threadIdx.x] : 0.f;
        for (int o = 4; o; o >>= 1) s += __shfl_xor_sync(FULLM, s, o);
        if (threadIdx.x == 0) tot = s;
    }
    __syncthreads();
    return tot;
}
DINLINE unsigned fkey(float v) {   // monotone float -> uint
    unsigned u = __float_as_uint(v);
    return (u & 0x80000000u) ? ~u : (u | 0x80000000u);
}

// ---------------- kernel 0: zero accumulators --------------------------------
__global__ void zero_k() {
    int i = blockIdx.x * blockDim.x + threadIdx.x;
    if (i < CC * CC) { g_psum[i] = 0.f; g_S[i] = 0.f; }
    if (i < CC) { g_colsum[i] = 0.f; g_cntall[i] = 0; g_cntlab[i] = 0; }
}

// ---------------- kernel 1: class id, rnorm, histograms ----------------------
__global__ void prep_k(const float* __restrict__ x, const float* __restrict__ labels) {
    __shared__ int s_all[CC], s_lab[CC];
    for (int i = threadIdx.x; i < CC; i += blockDim.x) { s_all[i] = 0; s_lab[i] = 0; }
    __syncthreads();
    int warp = threadIdx.x >> 5, lane = threadIdx.x & 31;
    int wpb = blockDim.x >> 5;
    for (int row = blockIdx.x * wpb + warp; row < NN; row += gridDim.x * wpb) {
        const float* lr = labels + (size_t)row * CC;
        int myc = -1;
        #pragma unroll
        for (int j = 0; j < 8; j++) {
            int c = lane + 32 * j;
            if (lr[c] > 0.5f) myc = c;
        }
        int cls = __reduce_max_sync(FULLM, myc);
        const float4* xr = (const float4*)(x + (size_t)row * CC);
        float ss = 0.f;
        #pragma unroll
        for (int j = 0; j < 2; j++) {
            float4 v = xr[lane + 32 * j];
            ss += v.x * v.x + v.y * v.y + v.z * v.z + v.w * v.w;
        }
        for (int o = 16; o; o >>= 1) ss += __shfl_xor_sync(FULLM, ss, o);
        if (lane == 0) {
            g_cls[row] = cls;
            g_rnorm[row] = rsqrtf(fmaxf(ss, 1e-12f));
            atomicAdd(&s_all[cls], 1);
            if (row < LL) atomicAdd(&s_lab[cls], 1);
        }
    }
    __syncthreads();
    for (int i = threadIdx.x; i < CC; i += blockDim.x) {
        if (s_all[i]) atomicAdd(&g_cntall[i], s_all[i]);
        if (s_lab[i]) atomicAdd(&g_cntlab[i], s_lab[i]);
    }
}

// ---------------- kernel 2: per-class labeled feature sums -------------------
constexpr int PSEG = 1568;  // 32 * 1568 >= LL
__global__ void paccum_k(const float* __restrict__ x) {
    __shared__ int s_cls[256];
    int cls = blockIdx.y;
    int n0 = blockIdx.x * PSEG;
    int n1 = min(n0 + PSEG, LL);
    int f = threadIdx.x;
    float acc = 0.f;
    for (int base = n0; base < n1; base += 256) {
        int nload = min(256, n1 - base);
        __syncthreads();
        if (f < nload) s_cls[f] = g_cls[base + f];
        __syncthreads();
        #pragma unroll 8
        for (int t = 0; t < nload; t++) {
            if (s_cls[t] == cls) acc += x[(size_t)(base + t) * CC + f];
        }
    }
    atomicAdd(&g_psum[cls * CC + f], acc);
}

// ---------------- kernel 3: protos + normalized protos -----------------------
__global__ void pfin_k() {
    int c = blockIdx.x, f = threadIdx.x;
    float v = g_psum[c * CC + f] / (float)g_cntall[c];
    g_protos[c * CC + f] = v;
    float tot = block_reduce_sum(v * v);
    g_protoN[c * CC + f] = v * rsqrtf(fmaxf(tot, 1e-12f));
}

// ---------------- GEMM: OUT[n][c] = rnorm[n] * (X[n][:] . protoN[c][:]) ------
// 64 rows x 256 cols per block, 256 threads, 8x8 micro-tile, f32x2 FMA.
__global__ void __launch_bounds__(256, 2)
gemm_xpt_k(const float* __restrict__ X, float* __restrict__ OUT,
           int rnoff, int nrows) {
    __shared__ float As[32][64];
    __shared__ float Bs[32][256];
    const float* __restrict__ P = g_protoN;
    const float* __restrict__ RN = g_rnorm + rnoff;
    float* __restrict__ O = OUT ? OUT : g_prob;
    int tid = threadIdx.x, tx = tid & 31, ty = tid >> 5;
    int n0 = blockIdx.x * 64;
    unsigned long long acc[8][4];
    #pragma unroll
    for (int i = 0; i < 8; i++)
        #pragma unroll
        for (int j = 0; j < 4; j++) acc[i][j] = 0ull;

    for (int f0 = 0; f0 < CC; f0 += 32) {
        #pragma unroll
        for (int q = 0; q < 2; q++) {
            int v = tid + 256 * q, row = v >> 3, fg = v & 7;
            float4 d = make_float4(0.f, 0.f, 0.f, 0.f);
            if (n0 + row < nrows)
                d = *(const float4*)(X + (size_t)(n0 + row) * CC + f0 + 4 * fg);
            As[4 * fg + 0][row] = d.x; As[4 * fg + 1][row] = d.y;
            As[4 * fg + 2][row] = d.z; As[4 * fg + 3][row] = d.w;
        }
        #pragma unroll
        for (int q = 0; q < 8; q++) {
            int v = tid + 256 * q, c = v >> 3, fg = v & 7;
            float4 d = *(const float4*)(P + (size_t)c * CC + f0 + 4 * fg);
            Bs[4 * fg + 0][c] = d.x; Bs[4 * fg + 1][c] = d.y;
            Bs[4 * fg + 2][c] = d.z; Bs[4 * fg + 3][c] = d.w;
        }
        __syncthreads();
        #pragma unroll
        for (int kk = 0; kk < 32; kk++) {
            float4 a0 = *(const float4*)&As[kk][8 * ty];
            float4 a1 = *(const float4*)&As[kk][8 * ty + 4];
            ulonglong2 b0 = *(const ulonglong2*)&Bs[kk][8 * tx];
            ulonglong2 b1 = *(const ulonglong2*)&Bs[kk][8 * tx + 4];
            float av[8] = {a0.x, a0.y, a0.z, a0.w, a1.x, a1.y, a1.z, a1.w};
            #pragma unroll
            for (int i = 0; i < 8; i++) {
                unsigned long long aa = bcast2(av[i]);
                acc[i][0] = ffma2(aa, b0.x, acc[i][0]);
                acc[i][1] = ffma2(aa, b0.y, acc[i][1]);
                acc[i][2] = ffma2(aa, b1.x, acc[i][2]);
                acc[i][3] = ffma2(aa, b1.y, acc[i][3]);
            }
        }
        __syncthreads();
    }
    #pragma unroll
    for (int i = 0; i < 8; i++) {
        int row = n0 + 8 * ty + i;
        if (row < nrows) {
            float rs = RN[row];
            float2 p0 = unpk(acc[i][0]), p1 = unpk(acc[i][1]);
            float2 p2 = unpk(acc[i][2]), p3 = unpk(acc[i][3]);
            float4 o0 = make_float4(p0.x * rs, p0.y * rs, p1.x * rs, p1.y * rs);
            float4 o1 = make_float4(p2.x * rs, p2.y * rs, p3.x * rs, p3.y * rs);
            float* op = O + (size_t)row * CC + 8 * tx;
            *(float4*)op = o0; *(float4*)(op + 4) = o1;
        }
    }
}

// ---------------- kernel: exact per-row top-k mask + column sums -------------
__global__ void topk_k() {
    __shared__ float cs[CC];
    for (int i = threadIdx.x; i < CC; i += blockDim.x) cs[i] = 0.f;
    __syncthreads();
    int warp = threadIdx.x >> 5, lane = threadIdx.x & 31;
    for (int row = blockIdx.x * 8 + warp; row < NU; row += gridDim.x * 8) {
        float* pr = g_prob + (size_t)row * CC;
        float v[8]; unsigned key[8];
        #pragma unroll
        for (int j = 0; j < 8; j++) { v[j] = pr[lane + 32 * j]; key[j] = fkey(v[j]); }
        unsigned T = 0;
        for (int b = 31; b >= 0; b--) {
            unsigned cand = T | (1u << b);
            int cnt = 0;
            #pragma unroll
            for (int j = 0; j < 8; j++) cnt += (key[j] >= cand);
            cnt = (int)__reduce_add_sync(FULLM, (unsigned)cnt);
            if (cnt >= KTOP) T = cand;
        }
        int gt = 0;
        #pragma unroll
        for (int j = 0; j < 8; j++) gt += (key[j] > T);
        gt = (int)__reduce_add_sync(FULLM, (unsigned)gt);
        int r = KTOP - gt;      // ties to keep (lowest indices first)
        int cum = 0;
        #pragma unroll
        for (int j = 0; j < 8; j++) {
            bool eq = (key[j] == T);
            unsigned bal = __ballot_sync(FULLM, eq);
            int pre = cum + __popc(bal & ((1u << lane) - 1u));
            bool keep = (key[j] > T) || (eq && pre < r);
            cum += __popc(bal);
            float o = keep ? v[j] : 0.f;
            pr[lane + 32 * j] = o;
            if (o != 0.f) atomicAdd(&cs[lane + 32 * j], o);
        }
    }
    __syncthreads();
    float c = cs[threadIdx.x];
    if (c != 0.f) atomicAdd(&g_colsum[threadIdx.x], c);
}

// ---------------- split-K GEMM: S[c][f] += sum_r p[r][c] * x[r][f] -----------
// blockIdx.y selects a 128-class half; blockIdx.x a row segment. 512 threads.
__global__ void __launch_bounds__(512, 1)
gemm_ptx_k(const float* __restrict__ X, int nrows) {
    __shared__ float As[16][128];
    __shared__ float Bs[16][256];
    const float* __restrict__ Pm = g_prob;
    int tid = threadIdx.x, tx = tid & 31, ty = tid >> 5;  // ty 0..15
    int c0 = blockIdx.y * 128;
    int r0 = blockIdx.x * SEGL2;
    int r1 = min(r0 + SEGL2, nrows);
    unsigned long long acc[8][4];
    #pragma unroll
    for (int i = 0; i < 8; i++)
        #pragma unroll
        for (int j = 0; j < 4; j++) acc[i][j] = 0ull;

    for (int r = r0; r < r1; r += 16) {
        {
            int rr = tid >> 5, cg = tid & 31, row = r + rr;
            float4 d = make_float4(0.f, 0.f, 0.f, 0.f);
            if (row < r1) d = *(const float4*)(Pm + (size_t)row * CC + c0 + 4 * cg);
            *(float4*)&As[rr][4 * cg] = d;
        }
        #pragma unroll
        for (int q = 0; q < 2; q++) {
            int u = tid + 512 * q, rr = u >> 6, fg = u & 63, row = r + rr;
            float4 d = make_float4(0.f, 0.f, 0.f, 0.f);
            if (row < r1) d = *(const float4*)(X + (size_t)row * CC + 4 * fg);
            *(float4*)&Bs[rr][4 * fg] = d;
        }
        __syncthreads();
        #pragma unroll
        for (int kk = 0; kk < 16; kk++) {
            float4 a0 = *(const float4*)&As[kk][8 * ty];
            float4 a1 = *(const float4*)&As[kk][8 * ty + 4];
            ulonglong2 b0 = *(const ulonglong2*)&Bs[kk][8 * tx];
            ulonglong2 b1 = *(const ulonglong2*)&Bs[kk][8 * tx + 4];
            float av[8] = {a0.x, a0.y, a0.z, a0.w, a1.x, a1.y, a1.z, a1.w};
            #pragma unroll
            for (int i = 0; i < 8; i++) {
                unsigned long long aa = bcast2(av[i]);
                acc[i][0] = ffma2(aa, b0.x, acc[i][0]);
                acc[i][1] = ffma2(aa, b0.y, acc[i][1]);
                acc[i][2] = ffma2(aa, b1.x, acc[i][2]);
                acc[i][3] = ffma2(aa, b1.y, acc[i][3]);
            }
        }
        __syncthreads();
    }
    #pragma unroll
    for (int i = 0; i < 8; i++) {
        int c = c0 + 8 * ty + i;
        float2 p0 = unpk(acc[i][0]), p1 = unpk(acc[i][1]);
        float2 p2 = unpk(acc[i][2]), p3 = unpk(acc[i][3]);
        float* sp = g_S + (size_t)c * CC + 8 * tx;
        atomicAdd(sp + 0, p0.x); atomicAdd(sp + 1, p0.y);
        atomicAdd(sp + 2, p1.x); atomicAdd(sp + 3, p1.y);
        atomicAdd(sp + 4, p2.x); atomicAdd(sp + 5, p2.y);
        atomicAdd(sp + 6, p3.x); atomicAdd(sp + 7, p3.y);
    }
}

// ---------------- kernel: proto update + renormalize -------------------------
__global__ void pfin2_k() {
    int c = blockIdx.x, f = threadIdx.x;
    float cp = g_colsum[c];
    float denom = cp + (float)g_cntlab[c];
    float pv = g_protos[c * CC + f];
    float nv = pv + g_S[c * CC + f] / denom - (cp / denom) * pv;
    float tot = block_reduce_sum(nv * nv);
    g_protoN[c * CC + f] = nv * rsqrtf(fmaxf(tot, 1e-12f));
}

// ---------------- launch ------------------------------------------------------
extern "C" void kernel_launch(void* const* d_in, const int* in_sizes, int n_in,
                              void* d_out, int out_size) {
    (void)in_sizes; (void)n_in; (void)out_size;
    const float* x = (const float*)d_in[0];
    const float* labels = (const float*)d_in[1];
    float* out = (float*)d_out;

    zero_k<<<CC, 256>>>();                                     // clear accumulators
    prep_k<<<1480, 256>>>(x, labels);                          // cls, rnorm, hists
    paccum_k<<<dim3(32, CC), 256>>>(x);                        // per-class sums
    pfin_k<<<CC, 256>>>();                                     // protos + protoN
    gemm_xpt_k<<<(NU + 63) / 64, 256>>>(x + (size_t)LL * CC,   // prob (unlabeled)
                                        nullptr, LL, NU);
    topk_k<<<1563, 256>>>();                                   // exact top-k + colsum
    gemm_ptx_k<<<dim3(74, 2), 512>>>(x + (size_t)LL * CC, NU); // S = p^T x
    pfin2_k<<<CC, 256>>>();                                    // proto update + norm
    gemm_xpt_k<<<(NN + 63) / 64, 256>>>(x, out, 0, NN);        // logits
}

// round 4
// speedup vs baseline: 1.4184x; 1.4184x over previous
#include <cuda_runtime.h>
#include <cuda_bf16.h>
#include <cstdint>

#define FULLM 0xffffffffu
#define DINLINE __device__ __forceinline__

constexpr int NN = 150000, CC = 256, LL = 50000, KTOP = 200;
constexpr int NU = NN - LL;
constexpr int SEGL2 = 1352;            // 74 * 1352 >= NU
// mma kernel smem: Ah/Al (2*10240) + B double buffer (2*20480) = 61440
constexpr int SMEM_MMA = 61440;

// ---------------- scratch (device globals; no allocation allowed) ------------
__device__ float g_prob[(size_t)NU * CC];
__device__ int   g_cls[NN];
__device__ float g_rnorm[NN];
__device__ float g_psum[CC * CC];
__device__ float g_protos[CC * CC];
__device__ float g_S[CC * CC];
__device__ float g_colsum[CC];
__device__ int   g_cntall[CC];
__device__ int   g_cntlab[CC];
// protoN as bf16 hi/lo smem-image: [chunk 8][hl 2][class 256][40 shorts (80B pitch)]
__device__ unsigned short g_Bimg[8 * 2 * 256 * 40];

// ---------------- helpers ----------------------------------------------------
DINLINE unsigned long long ffma2(unsigned long long a, unsigned long long b,
                                 unsigned long long c) {
    unsigned long long d;
    asm("fma.rn.f32x2 %0, %1, %2, %3;" : "=l"(d) : "l"(a), "l"(b), "l"(c));
    return d;
}
DINLINE unsigned long long bcast2(float f) {
    unsigned long long d; unsigned u = __float_as_uint(f);
    asm("mov.b64 %0, {%1, %1};" : "=l"(d) : "r"(u));
    return d;
}
DINLINE float2 unpk(unsigned long long u) {
    return make_float2(__uint_as_float((unsigned)(u & 0xffffffffull)),
                       __uint_as_float((unsigned)(u >> 32)));
}
DINLINE float block_reduce_sum(float v) {
    __shared__ float red[8];
    __shared__ float tot;
    for (int o = 16; o; o >>= 1) v += __shfl_xor_sync(FULLM, v, o);
    if ((threadIdx.x & 31) == 0) red[threadIdx.x >> 5] = v;
    __syncthreads();
    if (threadIdx.x < 32) {
        float s = (threadIdx.x < 8) ? red[threadIdx.x] : 0.f;
        for (int o = 4; o; o >>= 1) s += __shfl_xor_sync(FULLM, s, o);
        if (threadIdx.x == 0) tot = s;
    }
    __syncthreads();
    return tot;
}
DINLINE unsigned fkey(float v) {
    unsigned u = __float_as_uint(v);
    return (u & 0x80000000u) ? ~u : (u | 0x80000000u);
}
DINLINE uint32_t smem_u32(const void* p) {
    uint32_t a;
    asm("{ .reg .u64 t; cvta.to.shared.u64 t, %1; cvt.u32.u64 %0, t; }"
        : "=r"(a) : "l"(p));
    return a;
}
// pack two fp32 -> bf16x2 (hi arg -> upper 16 bits)
DINLINE uint32_t bf2pk(float hi, float lo) {
    uint32_t u;
    asm("cvt.rn.bf16x2.f32 %0, %1, %2;" : "=r"(u) : "f"(hi), "f"(lo));
    return u;
}
DINLINE void sts_u2(uint32_t addr, uint32_t a, uint32_t b) {
    asm volatile("st.shared.v2.b32 [%0], {%1, %2};" :: "r"(addr), "r"(a), "r"(b));
}
DINLINE void cpasync16(uint32_t dst, const void* src) {
    asm volatile("cp.async.ca.shared.global [%0], [%1], 16;"
                 :: "r"(dst), "l"(src));
}
#define CP_COMMIT() asm volatile("cp.async.commit_group;" ::: "memory")
#define CP_WAIT0()  asm volatile("cp.async.wait_group 0;" ::: "memory")

DINLINE void ldm_x4(uint32_t* r, uint32_t addr) {
    asm volatile("ldmatrix.sync.aligned.m8n8.x4.shared.b16 {%0,%1,%2,%3}, [%4];"
                 : "=r"(r[0]), "=r"(r[1]), "=r"(r[2]), "=r"(r[3]) : "r"(addr));
}
DINLINE void ldm_x2(uint32_t* r, uint32_t addr) {
    asm volatile("ldmatrix.sync.aligned.m8n8.x2.shared.b16 {%0,%1}, [%2];"
                 : "=r"(r[0]), "=r"(r[1]) : "r"(addr));
}
DINLINE void mma_bf16(float* c, const uint32_t* a, const uint32_t* b) {
    asm volatile(
        "mma.sync.aligned.m16n8k16.row.col.f32.bf16.bf16.f32 "
        "{%0,%1,%2,%3}, {%4,%5,%6,%7}, {%8,%9}, {%0,%1,%2,%3};"
        : "+f"(c[0]), "+f"(c[1]), "+f"(c[2]), "+f"(c[3])
        : "r"(a[0]), "r"(a[1]), "r"(a[2]), "r"(a[3]), "r"(b[0]), "r"(b[1]));
}

// ---------------- kernel 0: zero accumulators --------------------------------
__global__ void zero_k() {
    int i = blockIdx.x * blockDim.x + threadIdx.x;
    if (i < CC * CC) { g_psum[i] = 0.f; g_S[i] = 0.f; }
    if (i < CC) { g_colsum[i] = 0.f; g_cntall[i] = 0; g_cntlab[i] = 0; }
}

// ---------------- kernel 1: class id, rnorm, histograms ----------------------
__global__ void prep_k(const float* __restrict__ x, const float* __restrict__ labels) {
    __shared__ int s_all[CC], s_lab[CC];
    for (int i = threadIdx.x; i < CC; i += blockDim.x) { s_all[i] = 0; s_lab[i] = 0; }
    __syncthreads();
    int warp = threadIdx.x >> 5, lane = threadIdx.x & 31;
    int wpb = blockDim.x >> 5;
    for (int row = blockIdx.x * wpb + warp; row < NN; row += gridDim.x * wpb) {
        const float* lr = labels + (size_t)row * CC;
        int myc = -1;
        #pragma unroll
        for (int j = 0; j < 8; j++) {
            int c = lane + 32 * j;
            if (lr[c] > 0.5f) myc = c;
        }
        int cls = __reduce_max_sync(FULLM, myc);
        const float4* xr = (const float4*)(x + (size_t)row * CC);
        float ss = 0.f;
        #pragma unroll
        for (int j = 0; j < 2; j++) {
            float4 v = xr[lane + 32 * j];
            ss += v.x * v.x + v.y * v.y + v.z * v.z + v.w * v.w;
        }
        for (int o = 16; o; o >>= 1) ss += __shfl_xor_sync(FULLM, ss, o);
        if (lane == 0) {
            g_cls[row] = cls;
            g_rnorm[row] = rsqrtf(fmaxf(ss, 1e-12f));
            atomicAdd(&s_all[cls], 1);
            if (row < LL) atomicAdd(&s_lab[cls], 1);
        }
    }
    __syncthreads();
    for (int i = threadIdx.x; i < CC; i += blockDim.x) {
        if (s_all[i]) atomicAdd(&g_cntall[i], s_all[i]);
        if (s_lab[i]) atomicAdd(&g_cntlab[i], s_lab[i]);
    }
}

// ---------------- kernel 2: per-class labeled feature sums -------------------
constexpr int PSEG = 1568;
__global__ void paccum_k(const float* __restrict__ x) {
    __shared__ int s_cls[256];
    int cls = blockIdx.y;
    int n0 = blockIdx.x * PSEG;
    int n1 = min(n0 + PSEG, LL);
    int f = threadIdx.x;
    float acc = 0.f;
    for (int base = n0; base < n1; base += 256) {
        int nload = min(256, n1 - base);
        __syncthreads();
        if (f < nload) s_cls[f] = g_cls[base + f];
        __syncthreads();
        #pragma unroll 8
        for (int t = 0; t < nload; t++) {
            if (s_cls[t] == cls) acc += x[(size_t)(base + t) * CC + f];
        }
    }
    atomicAdd(&g_psum[cls * CC + f], acc);
}

// ---------------- write protoN split (bf16 hi/lo) into image -----------------
DINLINE void write_bimg(int c, int f, float v) {
    __nv_bfloat16 hb = __float2bfloat16_rn(v);
    float hf = __bfloat162float(hb);
    __nv_bfloat16 lb = __float2bfloat16_rn(v - hf);
    int ck = f >> 5, kl = f & 31;
    g_Bimg[((ck * 2 + 0) * 256 + c) * 40 + kl] = *(unsigned short*)&hb;
    g_Bimg[((ck * 2 + 1) * 256 + c) * 40 + kl] = *(unsigned short*)&lb;
}

// ---------------- kernel 3: protos + normalized protoN split -----------------
__global__ void pfin_k() {
    int c = blockIdx.x, f = threadIdx.x;
    float v = g_psum[c * CC + f] / (float)g_cntall[c];
    g_protos[c * CC + f] = v;
    float tot = block_reduce_sum(v * v);
    write_bimg(c, f, v * rsqrtf(fmaxf(tot, 1e-12f)));
}

// ---------------- mma.sync bf16x3 GEMM: OUT[n][c] = rnorm[n]*(X[n].pN[c]) ----
// block: 128 rows x 128 classes (grid.y=2), 8 warps, warp tile 64x32.
// K=256 in 8 chunks of 32. A: reg-prefetch + bf16 split; B: cp.async image.
__global__ void __launch_bounds__(256, 2)
gemm_mma_k(const float* __restrict__ X, float* __restrict__ OUT,
           int rnoff, int nrows) {
    extern __shared__ char dsm[];
    __shared__ float s_rn[128];
    const float* __restrict__ RN = g_rnorm + rnoff;
    float* __restrict__ O = OUT ? OUT : g_prob;

    const int tid = threadIdx.x, lane = tid & 31, wid = tid >> 5;
    const int wm = wid >> 2, wn = wid & 3;
    const int n0 = blockIdx.x * 128;
    const int c0 = blockIdx.y * 128;

    const uint32_t uA = smem_u32(dsm);         // Ah 10240, Al 10240
    const uint32_t uAl = uA + 10240;
    const uint32_t uB0 = uA + 20480;           // B buf0: H 10240 + L 10240
    const uint32_t uB1 = uA + 40960;           // B buf1

    if (tid < 128) {
        int r = n0 + tid;
        s_rn[tid] = (r < nrows) ? RN[r] : 0.f;
    }

    // per-lane ldmatrix address parts
    const int a_row = (lane & 7) + 8 * ((lane >> 3) & 1);
    const int a_kb  = 16 * (lane >> 4);
    const int b_row = lane & 7;
    const int b_kb  = 16 * ((lane >> 3) & 1);
    const uint32_t uAh_l = uA  + (uint32_t)((64 * wm + a_row) * 80 + a_kb);
    const uint32_t uAl_l = uAl + (uint32_t)((64 * wm + a_row) * 80 + a_kb);
    const uint32_t bofs  = (uint32_t)((32 * wn + b_row) * 80 + b_kb);

    float acc[4][4][4];
    #pragma unroll
    for (int i = 0; i < 4; i++)
        #pragma unroll
        for (int j = 0; j < 4; j++)
            #pragma unroll
            for (int q = 0; q < 4; q++) acc[i][j][q] = 0.f;

    // A staging: 128 rows x 8 float4/row = 1024 float4 -> 4 per thread
    const int am = tid >> 3, af4 = tid & 7;
    const uint32_t aAst = uA + (uint32_t)(am * 80 + 8 * af4);
    const bool aok[4] = { n0 + am +  0 < nrows, n0 + am + 32 < nrows,
                          n0 + am + 64 < nrows, n0 + am + 96 < nrows };
    const float4 z4 = make_float4(0.f, 0.f, 0.f, 0.f);

    float4 ga[4];
    #pragma unroll
    for (int q = 0; q < 4; q++)
        ga[q] = aok[q] ? *(const float4*)(X + (size_t)(n0 + am + 32 * q) * CC + 4 * af4)
                       : z4;
    // B chunk 0 -> buf0
    {
        const char* src = (const char*)g_Bimg + (size_t)(0 * 2 * 256 + c0) * 80;
        const char* srcL = (const char*)g_Bimg + (size_t)((0 * 2 + 1) * 256 + c0) * 80;
        #pragma unroll
        for (int s = 0; s < 5; s++) {
            int j = tid + 256 * s;
            if (j < 640) cpasync16(uB0 + 16 * j, src + 16 * j);
            else         cpasync16(uB0 + 16 * j, srcL + 16 * (j - 640));
        }
        CP_COMMIT();
    }

    for (int ck = 0; ck < 8; ck++) {
        // store prefetched A (split to bf16 hi/lo)
        #pragma unroll
        for (int q = 0; q < 4; q++) {
            uint32_t h0 = bf2pk(ga[q].y, ga[q].x), h1 = bf2pk(ga[q].w, ga[q].z);
            float f0 = __uint_as_float(h0 << 16);
            float f1 = __uint_as_float(h0 & 0xffff0000u);
            float f2 = __uint_as_float(h1 << 16);
            float f3 = __uint_as_float(h1 & 0xffff0000u);
            uint32_t l0 = bf2pk(ga[q].y - f1, ga[q].x - f0);
            uint32_t l1 = bf2pk(ga[q].w - f3, ga[q].z - f2);
            sts_u2(aAst + (uint32_t)(q * 32 * 80), h0, h1);
            sts_u2(aAst + (uint32_t)(q * 32 * 80) + 10240, l0, l1);
        }
        CP_WAIT0();
        __syncthreads();

        if (ck < 7) {
            int kf = (ck + 1) * 32;
            #pragma unroll
            for (int q = 0; q < 4; q++)
                ga[q] = aok[q] ? *(const float4*)(X + (size_t)(n0 + am + 32 * q) * CC
                                                  + kf + 4 * af4)
                               : z4;
            const char* src = (const char*)g_Bimg +
                (size_t)(((ck + 1) * 2 + 0) * 256 + c0) * 80;
            const char* srcL = (const char*)g_Bimg +
                (size_t)(((ck + 1) * 2 + 1) * 256 + c0) * 80;
            uint32_t dst = (ck & 1) ? uB0 : uB1;
            #pragma unroll
            for (int s = 0; s < 5; s++) {
                int j = tid + 256 * s;
                if (j < 640) cpasync16(dst + 16 * j, src + 16 * j);
                else         cpasync16(dst + 16 * j, srcL + 16 * (j - 640));
            }
            CP_COMMIT();
        }

        uint32_t ubh = ((ck & 1) ? uB1 : uB0) + bofs;
        uint32_t ubl = ubh + 10240;
        #pragma unroll
        for (int ks = 0; ks < 2; ks++) {
            uint32_t bh[4][2], bl[4][2];
            #pragma unroll
            for (int nf = 0; nf < 4; nf++) {
                ldm_x2(bh[nf], ubh + nf * 640 + ks * 32);
                ldm_x2(bl[nf], ubl + nf * 640 + ks * 32);
            }
            #pragma unroll
            for (int mf = 0; mf < 4; mf++) {
                uint32_t ah[4], al[4];
                ldm_x4(ah, uAh_l + mf * 1280 + ks * 32);
                ldm_x4(al, uAl_l + mf * 1280 + ks * 32);
                #pragma unroll
                for (int nf = 0; nf < 4; nf++) {
                    mma_bf16(acc[mf][nf], ah, bh[nf]);
                    mma_bf16(acc[mf][nf], al, bh[nf]);
                    mma_bf16(acc[mf][nf], ah, bl[nf]);
                }
            }
        }
        __syncthreads();
    }

    // -------- epilogue: scale by rnorm, direct float2 stores (32B sectors) ---
    #pragma unroll
    for (int mf = 0; mf < 4; mf++) {
        #pragma unroll
        for (int half = 0; half < 2; half++) {
            int rl = 64 * wm + 16 * mf + (lane >> 2) + 8 * half;
            int grow = n0 + rl;
            if (grow < nrows) {
                float rs = s_rn[rl];
                float* op = O + (size_t)grow * CC + c0 + 32 * wn + 2 * (lane & 3);
                #pragma unroll
                for (int nf = 0; nf < 4; nf++) {
                    float2 v = make_float2(acc[mf][nf][2 * half] * rs,
                                           acc[mf][nf][2 * half + 1] * rs);
                    *(float2*)(op + 8 * nf) = v;
                }
            }
        }
    }
}

// ---------------- kernel: exact per-row top-k mask + column sums -------------
__global__ void topk_k() {
    __shared__ float cs[CC];
    for (int i = threadIdx.x; i < CC; i += blockDim.x) cs[i] = 0.f;
    __syncthreads();
    int warp = threadIdx.x >> 5, lane = threadIdx.x & 31;
    for (int row = blockIdx.x * 8 + warp; row < NU; row += gridDim.x * 8) {
        float* pr = g_prob + (size_t)row * CC;
        float v[8]; unsigned key[8];
        #pragma unroll
        for (int j = 0; j < 8; j++) { v[j] = pr[lane + 32 * j]; key[j] = fkey(v[j]); }
        unsigned T = 0;
        for (int b = 31; b >= 0; b--) {
            unsigned cand = T | (1u << b);
            int cnt = 0;
            #pragma unroll
            for (int j = 0; j < 8; j++) cnt += (key[j] >= cand);
            cnt = (int)__reduce_add_sync(FULLM, (unsigned)cnt);
            if (cnt >= KTOP) T = cand;
        }
        int gt = 0;
        #pragma unroll
        for (int j = 0; j < 8; j++) gt += (key[j] > T);
        gt = (int)__reduce_add_sync(FULLM, (unsigned)gt);
        int r = KTOP - gt;
        int cum = 0;
        #pragma unroll
        for (int j = 0; j < 8; j++) {
            bool eq = (key[j] == T);
            unsigned bal = __ballot_sync(FULLM, eq);
            int pre = cum + __popc(bal & ((1u << lane) - 1u));
            bool keep = (key[j] > T) || (eq && pre < r);
            cum += __popc(bal);
            float o = keep ? v[j] : 0.f;
            pr[lane + 32 * j] = o;
            if (o != 0.f) atomicAdd(&cs[lane + 32 * j], o);
        }
    }
    __syncthreads();
    float c = cs[threadIdx.x];
    if (c != 0.f) atomicAdd(&g_colsum[threadIdx.x], c);
}

// ---------------- split-K GEMM: S[c][f] += sum_r p[r][c] * x[r][f] -----------
__global__ void __launch_bounds__(512, 1)
gemm_ptx_k(const float* __restrict__ X, int nrows) {
    __shared__ float As[16][128];
    __shared__ float Bs[16][256];
    const float* __restrict__ Pm = g_prob;
    int tid = threadIdx.x, tx = tid & 31, ty = tid >> 5;
    int c0 = blockIdx.y * 128;
    int r0 = blockIdx.x * SEGL2;
    int r1 = min(r0 + SEGL2, nrows);
    unsigned long long acc[8][4];
    #pragma unroll
    for (int i = 0; i < 8; i++)
        #pragma unroll
        for (int j = 0; j < 4; j++) acc[i][j] = 0ull;

    for (int r = r0; r < r1; r += 16) {
        {
            int rr = tid >> 5, cg = tid & 31, row = r + rr;
            float4 d = make_float4(0.f, 0.f, 0.f, 0.f);
            if (row < r1) d = *(const float4*)(Pm + (size_t)row * CC + c0 + 4 * cg);
            *(float4*)&As[rr][4 * cg] = d;
        }
        #pragma unroll
        for (int q = 0; q < 2; q++) {
            int u = tid + 512 * q, rr = u >> 6, fg = u & 63, row = r + rr;
            float4 d = make_float4(0.f, 0.f, 0.f, 0.f);
            if (row < r1) d = *(const float4*)(X + (size_t)row * CC + 4 * fg);
            *(float4*)&Bs[rr][4 * fg] = d;
        }
        __syncthreads();
        #pragma unroll
        for (int kk = 0; kk < 16; kk++) {
            float4 a0 = *(const float4*)&As[kk][8 * ty];
            float4 a1 = *(const float4*)&As[kk][8 * ty + 4];
            // conflict-free: 16B-stride contiguous per lane
            ulonglong2 b0 = *(const ulonglong2*)&Bs[kk][4 * tx];
            ulonglong2 b1 = *(const ulonglong2*)&Bs[kk][128 + 4 * tx];
            float av[8] = {a0.x, a0.y, a0.z, a0.w, a1.x, a1.y, a1.z, a1.w};
            #pragma unroll
            for (int i = 0; i < 8; i++) {
                unsigned long long aa = bcast2(av[i]);
                acc[i][0] = ffma2(aa, b0.x, acc[i][0]);
                acc[i][1] = ffma2(aa, b0.y, acc[i][1]);
                acc[i][2] = ffma2(aa, b1.x, acc[i][2]);
                acc[i][3] = ffma2(aa, b1.y, acc[i][3]);
            }
        }
        __syncthreads();
    }
    #pragma unroll
    for (int i = 0; i < 8; i++) {
        int c = c0 + 8 * ty + i;
        float2 p0 = unpk(acc[i][0]), p1 = unpk(acc[i][1]);
        float2 p2 = unpk(acc[i][2]), p3 = unpk(acc[i][3]);
        float* sp = g_S + (size_t)c * CC + 4 * tx;
        atomicAdd(sp + 0, p0.x); atomicAdd(sp + 1, p0.y);
        atomicAdd(sp + 2, p1.x); atomicAdd(sp + 3, p1.y);
        float* sq = sp + 128;
        atomicAdd(sq + 0, p2.x); atomicAdd(sq + 1, p2.y);
        atomicAdd(sq + 2, p3.x); atomicAdd(sq + 3, p3.y);
    }
}

// ---------------- kernel: proto update + renorm + split write ----------------
__global__ void pfin2_k() {
    int c = blockIdx.x, f = threadIdx.x;
    float cp = g_colsum[c];
    float denom = cp + (float)g_cntlab[c];
    float pv = g_protos[c * CC + f];
    float nv = pv + g_S[c * CC + f] / denom - (cp / denom) * pv;
    float tot = block_reduce_sum(nv * nv);
    write_bimg(c, f, nv * rsqrtf(fmaxf(tot, 1e-12f)));
}

// ---------------- launch ------------------------------------------------------
extern "C" void kernel_launch(void* const* d_in, const int* in_sizes, int n_in,
                              void* d_out, int out_size) {
    (void)in_sizes; (void)n_in; (void)out_size;
    const float* x = (const float*)d_in[0];
    const float* labels = (const float*)d_in[1];
    float* out = (float*)d_out;

    cudaFuncSetAttribute(gemm_mma_k, cudaFuncAttributeMaxDynamicSharedMemorySize,
                         SMEM_MMA);

    zero_k<<<CC, 256>>>();
    prep_k<<<1480, 256>>>(x, labels);
    paccum_k<<<dim3(32, CC), 256>>>(x);
    pfin_k<<<CC, 256>>>();
    gemm_mma_k<<<dim3((NU + 127) / 128, 2), 256, SMEM_MMA>>>(
        x + (size_t)LL * CC, nullptr, LL, NU);
    topk_k<<<1563, 256>>>();
    gemm_ptx_k<<<dim3(74, 2), 512>>>(x + (size_t)LL * CC, NU);
    pfin2_k<<<CC, 256>>>();
    gemm_mma_k<<<dim3((NN + 127) / 128, 2), 256, SMEM_MMA>>>(x, out, 0, NN);
}

// round 5
// speedup vs baseline: 3.3503x; 2.3620x over previous
#include <cuda_runtime.h>
#include <cuda_bf16.h>
#include <cstdint>

#define FULLM 0xffffffffu
#define DINLINE __device__ __forceinline__

constexpr int NN = 150000, CC = 256, LL = 50000, KTOP = 200;
constexpr int NU = NN - LL;
// mma xpt kernel smem: Ah/Al (2*10240) + B double buffer (2*20480) = 61440
constexpr int SMEM_MMA = 61440;
// ptx mma kernel: apT h/l (2*20480) + bxT h/l (2*10240) = 61440
constexpr int SMEM_PTX = 61440;
constexpr int SEGP = 1376;             // 43 chunks of 32 rows
constexpr int NSEGP = 73;              // 73 * 1376 = 100448 >= NU
constexpr int CHKP = 43;

// ---------------- scratch (device globals; no allocation allowed) ------------
__device__ float g_prob[(size_t)NU * CC];
__device__ int   g_cls[NN];
__device__ float g_rnorm[NN];
__device__ float g_psum[CC * CC];
__device__ float g_protos[CC * CC];
__device__ float g_S[CC * CC];
__device__ float g_colsum[CC];
__device__ int   g_cntall[CC];
__device__ int   g_cntlab[CC];
// protoN as bf16 hi/lo smem-image: [chunk 8][hl 2][class 256][40 shorts (80B pitch)]
__device__ unsigned short g_Bimg[8 * 2 * 256 * 40];

// ---------------- helpers ----------------------------------------------------
DINLINE float block_reduce_sum(float v) {
    __shared__ float red[8];
    __shared__ float tot;
    for (int o = 16; o; o >>= 1) v += __shfl_xor_sync(FULLM, v, o);
    if ((threadIdx.x & 31) == 0) red[threadIdx.x >> 5] = v;
    __syncthreads();
    if (threadIdx.x < 32) {
        float s = (threadIdx.x < 8) ? red[threadIdx.x] : 0.f;
        for (int o = 4; o; o >>= 1) s += __shfl_xor_sync(FULLM, s, o);
        if (threadIdx.x == 0) tot = s;
    }
    __syncthreads();
    return tot;
}
DINLINE unsigned fkey(float v) {
    unsigned u = __float_as_uint(v);
    return (u & 0x80000000u) ? ~u : (u | 0x80000000u);
}
DINLINE uint32_t smem_u32(const void* p) {
    uint32_t a;
    asm("{ .reg .u64 t; cvta.to.shared.u64 t, %1; cvt.u32.u64 %0, t; }"
        : "=r"(a) : "l"(p));
    return a;
}
DINLINE uint32_t bf2pk(float hi, float lo) {
    uint32_t u;
    asm("cvt.rn.bf16x2.f32 %0, %1, %2;" : "=r"(u) : "f"(hi), "f"(lo));
    return u;
}
DINLINE void sts_u2(uint32_t addr, uint32_t a, uint32_t b) {
    asm volatile("st.shared.v2.b32 [%0], {%1, %2};" :: "r"(addr), "r"(a), "r"(b));
}
DINLINE void sts16(uint32_t addr, unsigned short v) {
    asm volatile("st.shared.u16 [%0], %1;" :: "r"(addr), "h"(v));
}
// fp32 -> bf16 hi + bf16 lo residual
DINLINE void bsplit(float v, unsigned short& h, unsigned short& l) {
    __nv_bfloat16 hb = __float2bfloat16_rn(v);
    unsigned short hs = __bfloat16_as_ushort(hb);
    float hf = __uint_as_float((uint32_t)hs << 16);
    __nv_bfloat16 lb = __float2bfloat16_rn(v - hf);
    h = hs;
    l = __bfloat16_as_ushort(lb);
}
DINLINE void cpasync16(uint32_t dst, const void* src) {
    asm volatile("cp.async.ca.shared.global [%0], [%1], 16;"
                 :: "r"(dst), "l"(src));
}
#define CP_COMMIT() asm volatile("cp.async.commit_group;" ::: "memory")
#define CP_WAIT0()  asm volatile("cp.async.wait_group 0;" ::: "memory")

DINLINE void ldm_x4(uint32_t* r, uint32_t addr) {
    asm volatile("ldmatrix.sync.aligned.m8n8.x4.shared.b16 {%0,%1,%2,%3}, [%4];"
                 : "=r"(r[0]), "=r"(r[1]), "=r"(r[2]), "=r"(r[3]) : "r"(addr));
}
DINLINE void ldm_x2(uint32_t* r, uint32_t addr) {
    asm volatile("ldmatrix.sync.aligned.m8n8.x2.shared.b16 {%0,%1}, [%2];"
                 : "=r"(r[0]), "=r"(r[1]) : "r"(addr));
}
DINLINE void mma_bf16(float* c, const uint32_t* a, const uint32_t* b) {
    asm volatile(
        "mma.sync.aligned.m16n8k16.row.col.f32.bf16.bf16.f32 "
        "{%0,%1,%2,%3}, {%4,%5,%6,%7}, {%8,%9}, {%0,%1,%2,%3};"
        : "+f"(c[0]), "+f"(c[1]), "+f"(c[2]), "+f"(c[3])
        : "r"(a[0]), "r"(a[1]), "r"(a[2]), "r"(a[3]), "r"(b[0]), "r"(b[1]));
}

// ---------------- kernel 0: zero accumulators --------------------------------
__global__ void zero_k() {
    int i = blockIdx.x * blockDim.x + threadIdx.x;
    if (i < CC * CC) { g_psum[i] = 0.f; g_S[i] = 0.f; }
    if (i < CC) { g_colsum[i] = 0.f; g_cntall[i] = 0; g_cntlab[i] = 0; }
}

// ---------------- kernel 1: class id, rnorm, histograms ----------------------
__global__ void prep_k(const float* __restrict__ x, const float* __restrict__ labels) {
    __shared__ int s_all[CC], s_lab[CC];
    for (int i = threadIdx.x; i < CC; i += blockDim.x) { s_all[i] = 0; s_lab[i] = 0; }
    __syncthreads();
    int warp = threadIdx.x >> 5, lane = threadIdx.x & 31;
    int wpb = blockDim.x >> 5;
    for (int row = blockIdx.x * wpb + warp; row < NN; row += gridDim.x * wpb) {
        const float* lr = labels + (size_t)row * CC;
        int myc = -1;
        #pragma unroll
        for (int j = 0; j < 8; j++) {
            int c = lane + 32 * j;
            if (lr[c] > 0.5f) myc = c;
        }
        int cls = __reduce_max_sync(FULLM, myc);
        const float4* xr = (const float4*)(x + (size_t)row * CC);
        float ss = 0.f;
        #pragma unroll
        for (int j = 0; j < 2; j++) {
            float4 v = xr[lane + 32 * j];
            ss += v.x * v.x + v.y * v.y + v.z * v.z + v.w * v.w;
        }
        for (int o = 16; o; o >>= 1) ss += __shfl_xor_sync(FULLM, ss, o);
        if (lane == 0) {
            g_cls[row] = cls;
            g_rnorm[row] = rsqrtf(fmaxf(ss, 1e-12f));
            atomicAdd(&s_all[cls], 1);
            if (row < LL) atomicAdd(&s_lab[cls], 1);
        }
    }
    __syncthreads();
    for (int i = threadIdx.x; i < CC; i += blockDim.x) {
        if (s_all[i]) atomicAdd(&g_cntall[i], s_all[i]);
        if (s_lab[i]) atomicAdd(&g_cntlab[i], s_lab[i]);
    }
}

// ---------------- kernel 2: per-class labeled feature sums (atomic) ----------
__global__ void paccum_k(const float* __restrict__ x) {
    int row = blockIdx.x;
    int f = threadIdx.x;
    int cls = g_cls[row];
    atomicAdd(&g_psum[cls * CC + f], x[(size_t)row * CC + f]);
}

// ---------------- write protoN split (bf16 hi/lo) into image -----------------
DINLINE void write_bimg(int c, int f, float v) {
    unsigned short h, l;
    bsplit(v, h, l);
    int ck = f >> 5, kl = f & 31;
    g_Bimg[((ck * 2 + 0) * 256 + c) * 40 + kl] = h;
    g_Bimg[((ck * 2 + 1) * 256 + c) * 40 + kl] = l;
}

// ---------------- kernel 3: protos + normalized protoN split -----------------
__global__ void pfin_k() {
    int c = blockIdx.x, f = threadIdx.x;
    float v = g_psum[c * CC + f] / (float)g_cntall[c];
    g_protos[c * CC + f] = v;
    float tot = block_reduce_sum(v * v);
    write_bimg(c, f, v * rsqrtf(fmaxf(tot, 1e-12f)));
}

// ---------------- mma.sync bf16x3 GEMM: OUT[n][c] = rnorm[n]*(X[n].pN[c]) ----
__global__ void __launch_bounds__(256, 2)
gemm_mma_k(const float* __restrict__ X, float* __restrict__ OUT,
           int rnoff, int nrows) {
    extern __shared__ char dsm[];
    __shared__ float s_rn[128];
    const float* __restrict__ RN = g_rnorm + rnoff;
    float* __restrict__ O = OUT ? OUT : g_prob;

    const int tid = threadIdx.x, lane = tid & 31, wid = tid >> 5;
    const int wm = wid >> 2, wn = wid & 3;
    const int n0 = blockIdx.x * 128;
    const int c0 = blockIdx.y * 128;

    const uint32_t uA = smem_u32(dsm);
    const uint32_t uAl = uA + 10240;
    const uint32_t uB0 = uA + 20480;
    const uint32_t uB1 = uA + 40960;

    if (tid < 128) {
        int r = n0 + tid;
        s_rn[tid] = (r < nrows) ? RN[r] : 0.f;
    }

    const int a_row = (lane & 7) + 8 * ((lane >> 3) & 1);
    const int a_kb  = 16 * (lane >> 4);
    const int b_row = lane & 7;
    const int b_kb  = 16 * ((lane >> 3) & 1);
    const uint32_t uAh_l = uA  + (uint32_t)((64 * wm + a_row) * 80 + a_kb);
    const uint32_t uAl_l = uAl + (uint32_t)((64 * wm + a_row) * 80 + a_kb);
    const uint32_t bofs  = (uint32_t)((32 * wn + b_row) * 80 + b_kb);

    float acc[4][4][4];
    #pragma unroll
    for (int i = 0; i < 4; i++)
        #pragma unroll
        for (int j = 0; j < 4; j++)
            #pragma unroll
            for (int q = 0; q < 4; q++) acc[i][j][q] = 0.f;

    const int am = tid >> 3, af4 = tid & 7;
    const uint32_t aAst = uA + (uint32_t)(am * 80 + 8 * af4);
    const bool aok[4] = { n0 + am +  0 < nrows, n0 + am + 32 < nrows,
                          n0 + am + 64 < nrows, n0 + am + 96 < nrows };
    const float4 z4 = make_float4(0.f, 0.f, 0.f, 0.f);

    float4 ga[4];
    #pragma unroll
    for (int q = 0; q < 4; q++)
        ga[q] = aok[q] ? *(const float4*)(X + (size_t)(n0 + am + 32 * q) * CC + 4 * af4)
                       : z4;
    {
        const char* src = (const char*)g_Bimg + (size_t)(0 * 2 * 256 + c0) * 80;
        const char* srcL = (const char*)g_Bimg + (size_t)((0 * 2 + 1) * 256 + c0) * 80;
        #pragma unroll
        for (int s = 0; s < 5; s++) {
            int j = tid + 256 * s;
            if (j < 640) cpasync16(uB0 + 16 * j, src + 16 * j);
            else         cpasync16(uB0 + 16 * j, srcL + 16 * (j - 640));
        }
        CP_COMMIT();
    }

    for (int ck = 0; ck < 8; ck++) {
        #pragma unroll
        for (int q = 0; q < 4; q++) {
            uint32_t h0 = bf2pk(ga[q].y, ga[q].x), h1 = bf2pk(ga[q].w, ga[q].z);
            float f0 = __uint_as_float(h0 << 16);
            float f1 = __uint_as_float(h0 & 0xffff0000u);
            float f2 = __uint_as_float(h1 << 16);
            float f3 = __uint_as_float(h1 & 0xffff0000u);
            uint32_t l0 = bf2pk(ga[q].y - f1, ga[q].x - f0);
            uint32_t l1 = bf2pk(ga[q].w - f3, ga[q].z - f2);
            sts_u2(aAst + (uint32_t)(q * 32 * 80), h0, h1);
            sts_u2(aAst + (uint32_t)(q * 32 * 80) + 10240, l0, l1);
        }
        CP_WAIT0();
        __syncthreads();

        if (ck < 7) {
            int kf = (ck + 1) * 32;
            #pragma unroll
            for (int q = 0; q < 4; q++)
                ga[q] = aok[q] ? *(const float4*)(X + (size_t)(n0 + am + 32 * q) * CC
                                                  + kf + 4 * af4)
                               : z4;
            const char* src = (const char*)g_Bimg +
                (size_t)(((ck + 1) * 2 + 0) * 256 + c0) * 80;
            const char* srcL = (const char*)g_Bimg +
                (size_t)(((ck + 1) * 2 + 1) * 256 + c0) * 80;
            uint32_t dst = (ck & 1) ? uB0 : uB1;
            #pragma unroll
            for (int s = 0; s < 5; s++) {
                int j = tid + 256 * s;
                if (j < 640) cpasync16(dst + 16 * j, src + 16 * j);
                else         cpasync16(dst + 16 * j, srcL + 16 * (j - 640));
            }
            CP_COMMIT();
        }

        uint32_t ubh = ((ck & 1) ? uB1 : uB0) + bofs;
        uint32_t ubl = ubh + 10240;
        #pragma unroll
        for (int ks = 0; ks < 2; ks++) {
            uint32_t bh[4][2], bl[4][2];
            #pragma unroll
            for (int nf = 0; nf < 4; nf++) {
                ldm_x2(bh[nf], ubh + nf * 640 + ks * 32);
                ldm_x2(bl[nf], ubl + nf * 640 + ks * 32);
            }
            #pragma unroll
            for (int mf = 0; mf < 4; mf++) {
                uint32_t ah[4], al[4];
                ldm_x4(ah, uAh_l + mf * 1280 + ks * 32);
                ldm_x4(al, uAl_l + mf * 1280 + ks * 32);
                #pragma unroll
                for (int nf = 0; nf < 4; nf++) {
                    mma_bf16(acc[mf][nf], ah, bh[nf]);
                    mma_bf16(acc[mf][nf], al, bh[nf]);
                    mma_bf16(acc[mf][nf], ah, bl[nf]);
                }
            }
        }
        __syncthreads();
    }

    #pragma unroll
    for (int mf = 0; mf < 4; mf++) {
        #pragma unroll
        for (int half = 0; half < 2; half++) {
            int rl = 64 * wm + 16 * mf + (lane >> 2) + 8 * half;
            int grow = n0 + rl;
            if (grow < nrows) {
                float rs = s_rn[rl];
                float* op = O + (size_t)grow * CC + c0 + 32 * wn + 2 * (lane & 3);
                #pragma unroll
                for (int nf = 0; nf < 4; nf++) {
                    float2 v = make_float2(acc[mf][nf][2 * half] * rs,
                                           acc[mf][nf][2 * half + 1] * rs);
                    *(float2*)(op + 8 * nf) = v;
                }
            }
        }
    }
}

// ---------------- kernel: exact per-row top-k mask + column sums -------------
__global__ void topk_k() {
    __shared__ float cs[CC];
    for (int i = threadIdx.x; i < CC; i += blockDim.x) cs[i] = 0.f;
    __syncthreads();
    int warp = threadIdx.x >> 5, lane = threadIdx.x & 31;
    for (int row = blockIdx.x * 8 + warp; row < NU; row += gridDim.x * 8) {
        float* pr = g_prob + (size_t)row * CC;
        float v[8]; unsigned key[8];
        #pragma unroll
        for (int j = 0; j < 8; j++) { v[j] = pr[lane + 32 * j]; key[j] = fkey(v[j]); }
        unsigned T = 0;
        for (int b = 31; b >= 0; b--) {
            unsigned cand = T | (1u << b);
            int cnt = 0;
            #pragma unroll
            for (int j = 0; j < 8; j++) cnt += (key[j] >= cand);
            cnt = (int)__reduce_add_sync(FULLM, (unsigned)cnt);
            if (cnt >= KTOP) T = cand;
        }
        int gt = 0;
        #pragma unroll
        for (int j = 0; j < 8; j++) gt += (key[j] > T);
        gt = (int)__reduce_add_sync(FULLM, (unsigned)gt);
        int r = KTOP - gt;
        int cum = 0;
        #pragma unroll
        for (int j = 0; j < 8; j++) {
            bool eq = (key[j] == T);
            unsigned bal = __ballot_sync(FULLM, eq);
            int pre = cum + __popc(bal & ((1u << lane) - 1u));
            bool keep = (key[j] > T) || (eq && pre < r);
            cum += __popc(bal);
            float o = keep ? v[j] : 0.f;
            pr[lane + 32 * j] = o;
            if (o != 0.f) atomicAdd(&cs[lane + 32 * j], o);
        }
    }
    __syncthreads();
    float c = cs[threadIdx.x];
    if (c != 0.f) atomicAdd(&g_colsum[threadIdx.x], c);
}

// ---------------- split-K bf16x3 mma GEMM: S[c][f] += sum_r p[r][c]*x[r][f] --
// Tile: M=256 classes x N=128 features (grid.y=2), K = SEGP rows per block.
// Both operands staged TRANSPOSED ([col][r], 80B pitch) during bf16 split.
__global__ void __launch_bounds__(512, 1)
gemm_ptx_mma_k(const float* __restrict__ X) {
    extern __shared__ char dsm[];
    const uint32_t uAh = smem_u32(dsm);       // apT hi: 256 x 80B
    const uint32_t uAl = uAh + 20480;         // apT lo
    const uint32_t uBh = uAh + 40960;         // bxT hi: 128 x 80B
    const uint32_t uBl = uAh + 51200;         // bxT lo

    const int tid = threadIdx.x, lane = tid & 31, wid = tid >> 5;
    const int wm = wid >> 2, wn = wid & 3;    // wm 0..3 (64c), wn 0..3 (32f)
    const int f0 = blockIdx.y * 128;
    const int R0 = blockIdx.x * SEGP;

    const int a_row = (lane & 7) + 8 * ((lane >> 3) & 1);
    const int a_kb  = 16 * (lane >> 4);
    const int b_row = lane & 7;
    const int b_kb  = 16 * ((lane >> 3) & 1);
    const uint32_t uAh_l = uAh + (uint32_t)((64 * wm + a_row) * 80 + a_kb);
    const uint32_t uAl_l = uAl + (uint32_t)((64 * wm + a_row) * 80 + a_kb);
    const uint32_t bofs  = (uint32_t)((32 * wn + b_row) * 80 + b_kb);

    float acc[4][4][4];
    #pragma unroll
    for (int i = 0; i < 4; i++)
        #pragma unroll
        for (int j = 0; j < 4; j++)
            #pragma unroll
            for (int q = 0; q < 4; q++) acc[i][j][q] = 0.f;

    // staging map: r = tid&31 (row within chunk), scg = tid>>5 (0..15)
    const int sr = tid & 31, scg = tid >> 5;
    const float4 z4 = make_float4(0.f, 0.f, 0.f, 0.f);

    float4 pv[4], xv[2];
    {
        int gr = R0 + sr;
        bool ok = gr < NU;
        const float4* prow = (const float4*)(g_prob + (size_t)gr * CC);
        const float4* xrow = (const float4*)(X + (size_t)gr * CC + f0);
        #pragma unroll
        for (int j = 0; j < 4; j++) pv[j] = ok ? prow[scg * 4 + j] : z4;
        #pragma unroll
        for (int j = 0; j < 2; j++) xv[j] = ok ? xrow[scg * 2 + j] : z4;
    }

    for (int ck = 0; ck < CHKP; ck++) {
        // transpose-store: apT[c][sr], bxT[f][sr]
        const float* pf = (const float*)pv;
        #pragma unroll
        for (int j = 0; j < 16; j++) {
            unsigned short h, l;
            bsplit(pf[j], h, l);
            uint32_t ad = (uint32_t)((scg * 16 + j) * 80 + 2 * sr);
            sts16(uAh + ad, h);
            sts16(uAl + ad, l);
        }
        const float* xf = (const float*)xv;
        #pragma unroll
        for (int j = 0; j < 8; j++) {
            unsigned short h, l;
            bsplit(xf[j], h, l);
            uint32_t ad = (uint32_t)((scg * 8 + j) * 80 + 2 * sr);
            sts16(uBh + ad, h);
            sts16(uBl + ad, l);
        }
        __syncthreads();

        if (ck + 1 < CHKP) {
            int gr = R0 + (ck + 1) * 32 + sr;
            bool ok = gr < NU;
            const float4* prow = (const float4*)(g_prob + (size_t)gr * CC);
            const float4* xrow = (const float4*)(X + (size_t)gr * CC + f0);
            #pragma unroll
            for (int j = 0; j < 4; j++) pv[j] = ok ? prow[scg * 4 + j] : z4;
            #pragma unroll
            for (int j = 0; j < 2; j++) xv[j] = ok ? xrow[scg * 2 + j] : z4;
        }

        #pragma unroll
        for (int ks = 0; ks < 2; ks++) {
            uint32_t bh[4][2], bl[4][2];
            #pragma unroll
            for (int nf = 0; nf < 4; nf++) {
                ldm_x2(bh[nf], uBh + bofs + nf * 640 + ks * 32);
                ldm_x2(bl[nf], uBl + bofs + nf * 640 + ks * 32);
            }
            #pragma unroll
            for (int mf = 0; mf < 4; mf++) {
                uint32_t ah[4], al[4];
                ldm_x4(ah, uAh_l + mf * 1280 + ks * 32);
                ldm_x4(al, uAl_l + mf * 1280 + ks * 32);
                #pragma unroll
                for (int nf = 0; nf < 4; nf++) {
                    mma_bf16(acc[mf][nf], ah, bh[nf]);
                    mma_bf16(acc[mf][nf], al, bh[nf]);
                    mma_bf16(acc[mf][nf], ah, bl[nf]);
                }
            }
        }
        __syncthreads();
    }

    // epilogue: atomic accumulate into g_S
    #pragma unroll
    for (int mf = 0; mf < 4; mf++) {
        #pragma unroll
        for (int nf = 0; nf < 4; nf++) {
            #pragma unroll
            for (int half = 0; half < 2; half++) {
                int c = 64 * wm + 16 * mf + (lane >> 2) + 8 * half;
                int f = f0 + 32 * wn + 8 * nf + 2 * (lane & 3);
                atomicAdd(&g_S[c * CC + f + 0], acc[mf][nf][2 * half + 0]);
                atomicAdd(&g_S[c * CC + f + 1], acc[mf][nf][2 * half + 1]);
            }
        }
    }
}

// ---------------- kernel: proto update + renorm + split write ----------------
__global__ void pfin2_k() {
    int c = blockIdx.x, f = threadIdx.x;
    float cp = g_colsum[c];
    float denom = cp + (float)g_cntlab[c];
    float pv = g_protos[c * CC + f];
    float nv = pv + g_S[c * CC + f] / denom - (cp / denom) * pv;
    float tot = block_reduce_sum(nv * nv);
    write_bimg(c, f, nv * rsqrtf(fmaxf(tot, 1e-12f)));
}

// ---------------- launch ------------------------------------------------------
extern "C" void kernel_launch(void* const* d_in, const int* in_sizes, int n_in,
                              void* d_out, int out_size) {
    (void)in_sizes; (void)n_in; (void)out_size;
    const float* x = (const float*)d_in[0];
    const float* labels = (const float*)d_in[1];
    float* out = (float*)d_out;

    cudaFuncSetAttribute(gemm_mma_k, cudaFuncAttributeMaxDynamicSharedMemorySize,
                         SMEM_MMA);
    cudaFuncSetAttribute(gemm_ptx_mma_k,
                         cudaFuncAttributeMaxDynamicSharedMemorySize, SMEM_PTX);

    zero_k<<<CC, 256>>>();
    prep_k<<<1480, 256>>>(x, labels);
    paccum_k<<<LL, 256>>>(x);
    pfin_k<<<CC, 256>>>();
    gemm_mma_k<<<dim3((NU + 127) / 128, 2), 256, SMEM_MMA>>>(
        x + (size_t)LL * CC, nullptr, LL, NU);
    topk_k<<<1563, 256>>>();
    gemm_ptx_mma_k<<<dim3(NSEGP, 2), 512, SMEM_PTX>>>(x + (size_t)LL * CC);
    pfin2_k<<<CC, 256>>>();
    gemm_mma_k<<<dim3((NN + 127) / 128, 2), 256, SMEM_MMA>>>(x, out, 0, NN);
}

// round 6
// speedup vs baseline: 3.6004x; 1.0747x over previous
#include <cuda_runtime.h>
#include <cuda_bf16.h>
#include <cstdint>

#define FULLM 0xffffffffu
#define DINLINE __device__ __forceinline__

constexpr int NN = 150000, CC = 256, LL = 50000, KTOP = 200;
constexpr int NU = NN - LL;
// mma xpt kernel smem: Ah/Al (2*10240) + B double buffer (2*20480) = 61440
constexpr int SMEM_MMA = 61440;
constexpr int SEGP = 1376;             // 43 chunks of 32 rows
constexpr int NSEGP = 73;              // 73 * 1376 = 100448 >= NU
constexpr int CHKP = 43;
constexpr int NPAD = NSEGP * SEGP;     // 100448 padded rows for images
// ptx mma kernel smem: per stage ph(16896)+pl(16896)+xh(8704)+xl(8704)=51200, x2
constexpr int SMEM_PTX = 102400;

// ---------------- scratch (device globals; no allocation allowed) ------------
__device__ float g_prob[(size_t)NU * CC];
__device__ int   g_cls[NN];
__device__ float g_rnorm[NN];
__device__ float g_psum[CC * CC];
__device__ float g_protos[CC * CC];
__device__ float g_S[CC * CC];
__device__ float g_colsum[CC];
__device__ int   g_cntall[CC];
__device__ int   g_cntlab[CC];
// protoN as bf16 hi/lo smem-image: [chunk 8][hl 2][class 256][40 shorts (80B pitch)]
__device__ unsigned short g_Bimg[8 * 2 * 256 * 40];
// masked-p bf16 hi/lo images [row][256] (pad rows stay zero-initialized)
__device__ __align__(16) unsigned short g_Ph[(size_t)NPAD * CC];
__device__ __align__(16) unsigned short g_Pl[(size_t)NPAD * CC];
// raw-x (unlabeled rows) bf16 hi/lo images [row][256]
__device__ __align__(16) unsigned short g_Xbh[(size_t)NPAD * CC];
__device__ __align__(16) unsigned short g_Xbl[(size_t)NPAD * CC];

// ---------------- helpers ----------------------------------------------------
DINLINE float block_reduce_sum(float v) {
    __shared__ float red[8];
    __shared__ float tot;
    for (int o = 16; o; o >>= 1) v += __shfl_xor_sync(FULLM, v, o);
    if ((threadIdx.x & 31) == 0) red[threadIdx.x >> 5] = v;
    __syncthreads();
    if (threadIdx.x < 32) {
        float s = (threadIdx.x < 8) ? red[threadIdx.x] : 0.f;
        for (int o = 4; o; o >>= 1) s += __shfl_xor_sync(FULLM, s, o);
        if (threadIdx.x == 0) tot = s;
    }
    __syncthreads();
    return tot;
}
DINLINE unsigned fkey(float v) {
    unsigned u = __float_as_uint(v);
    return (u & 0x80000000u) ? ~u : (u | 0x80000000u);
}
DINLINE uint32_t smem_u32(const void* p) {
    uint32_t a;
    asm("{ .reg .u64 t; cvta.to.shared.u64 t, %1; cvt.u32.u64 %0, t; }"
        : "=r"(a) : "l"(p));
    return a;
}
DINLINE uint32_t bf2pk(float hi, float lo) {   // hi -> upper 16 bits
    uint32_t u;
    asm("cvt.rn.bf16x2.f32 %0, %1, %2;" : "=r"(u) : "f"(hi), "f"(lo));
    return u;
}
DINLINE void sts_u2(uint32_t addr, uint32_t a, uint32_t b) {
    asm volatile("st.shared.v2.b32 [%0], {%1, %2};" :: "r"(addr), "r"(a), "r"(b));
}
DINLINE void bsplit(float v, unsigned short& h, unsigned short& l) {
    __nv_bfloat16 hb = __float2bfloat16_rn(v);
    unsigned short hs = __bfloat16_as_ushort(hb);
    float hf = __uint_as_float((uint32_t)hs << 16);
    __nv_bfloat16 lb = __float2bfloat16_rn(v - hf);
    h = hs;
    l = __bfloat16_as_ushort(lb);
}
DINLINE void cpasync16(uint32_t dst, const void* src) {
    asm volatile("cp.async.ca.shared.global [%0], [%1], 16;"
                 :: "r"(dst), "l"(src));
}
#define CP_COMMIT() asm volatile("cp.async.commit_group;" ::: "memory")
#define CP_WAIT0()  asm volatile("cp.async.wait_group 0;" ::: "memory")
#define CP_WAIT1()  asm volatile("cp.async.wait_group 1;" ::: "memory")

DINLINE void ldm_x4(uint32_t* r, uint32_t addr) {
    asm volatile("ldmatrix.sync.aligned.m8n8.x4.shared.b16 {%0,%1,%2,%3}, [%4];"
                 : "=r"(r[0]), "=r"(r[1]), "=r"(r[2]), "=r"(r[3]) : "r"(addr));
}
DINLINE void ldm_x2(uint32_t* r, uint32_t addr) {
    asm volatile("ldmatrix.sync.aligned.m8n8.x2.shared.b16 {%0,%1}, [%2];"
                 : "=r"(r[0]), "=r"(r[1]) : "r"(addr));
}
DINLINE void ldmT_x4(uint32_t* r, uint32_t addr) {
    asm volatile("ldmatrix.sync.aligned.m8n8.x4.trans.shared.b16 {%0,%1,%2,%3}, [%4];"
                 : "=r"(r[0]), "=r"(r[1]), "=r"(r[2]), "=r"(r[3]) : "r"(addr));
}
DINLINE void ldmT_x2(uint32_t* r, uint32_t addr) {
    asm volatile("ldmatrix.sync.aligned.m8n8.x2.trans.shared.b16 {%0,%1}, [%2];"
                 : "=r"(r[0]), "=r"(r[1]) : "r"(addr));
}
DINLINE void mma_bf16(float* c, const uint32_t* a, const uint32_t* b) {
    asm volatile(
        "mma.sync.aligned.m16n8k16.row.col.f32.bf16.bf16.f32 "
        "{%0,%1,%2,%3}, {%4,%5,%6,%7}, {%8,%9}, {%0,%1,%2,%3};"
        : "+f"(c[0]), "+f"(c[1]), "+f"(c[2]), "+f"(c[3])
        : "r"(a[0]), "r"(a[1]), "r"(a[2]), "r"(a[3]), "r"(b[0]), "r"(b[1]));
}

// ---------------- kernel 0: zero accumulators --------------------------------
__global__ void zero_k() {
    int i = blockIdx.x * blockDim.x + threadIdx.x;
    if (i < CC * CC) { g_psum[i] = 0.f; g_S[i] = 0.f; }
    if (i < CC) { g_colsum[i] = 0.f; g_cntall[i] = 0; g_cntlab[i] = 0; }
}

// ---------------- kernel 1: class id, rnorm, hist + x bf16 image -------------
__global__ void prep_k(const float* __restrict__ x, const float* __restrict__ labels) {
    __shared__ int s_all[CC], s_lab[CC];
    for (int i = threadIdx.x; i < CC; i += blockDim.x) { s_all[i] = 0; s_lab[i] = 0; }
    __syncthreads();
    int warp = threadIdx.x >> 5, lane = threadIdx.x & 31;
    int wpb = blockDim.x >> 5;
    for (int row = blockIdx.x * wpb + warp; row < NN; row += gridDim.x * wpb) {
        const float* lr = labels + (size_t)row * CC;
        int myc = -1;
        #pragma unroll
        for (int j = 0; j < 8; j++) {
            int c = lane + 32 * j;
            if (lr[c] > 0.5f) myc = c;
        }
        int cls = __reduce_max_sync(FULLM, myc);
        const float4* xr = (const float4*)(x + (size_t)row * CC);
        float ss = 0.f;
        float4 v[2];
        #pragma unroll
        for (int j = 0; j < 2; j++) {
            v[j] = xr[lane + 32 * j];
            ss += v[j].x * v[j].x + v[j].y * v[j].y + v[j].z * v[j].z + v[j].w * v[j].w;
        }
        for (int o = 16; o; o >>= 1) ss += __shfl_xor_sync(FULLM, ss, o);
        if (lane == 0) {
            g_cls[row] = cls;
            g_rnorm[row] = rsqrtf(fmaxf(ss, 1e-12f));
            atomicAdd(&s_all[cls], 1);
            if (row < LL) atomicAdd(&s_lab[cls], 1);
        }
        if (row >= LL) {   // write raw-x bf16 split image (unlabeled rows)
            size_t ur = (size_t)(row - LL) * CC;
            #pragma unroll
            for (int j = 0; j < 2; j++) {
                int fb = 4 * (lane + 32 * j);
                uint32_t h0 = bf2pk(v[j].y, v[j].x), h1 = bf2pk(v[j].w, v[j].z);
                float f0 = __uint_as_float(h0 << 16);
                float f1 = __uint_as_float(h0 & 0xffff0000u);
                float f2 = __uint_as_float(h1 << 16);
                float f3 = __uint_as_float(h1 & 0xffff0000u);
                uint32_t l0 = bf2pk(v[j].y - f1, v[j].x - f0);
                uint32_t l1 = bf2pk(v[j].w - f3, v[j].z - f2);
                *(uint2*)(g_Xbh + ur + fb) = make_uint2(h0, h1);
                *(uint2*)(g_Xbl + ur + fb) = make_uint2(l0, l1);
            }
        }
    }
    __syncthreads();
    for (int i = threadIdx.x; i < CC; i += blockDim.x) {
        if (s_all[i]) atomicAdd(&g_cntall[i], s_all[i]);
        if (s_lab[i]) atomicAdd(&g_cntlab[i], s_lab[i]);
    }
}

// ---------------- kernel 2: per-class labeled feature sums (atomic) ----------
__global__ void paccum_k(const float* __restrict__ x) {
    int row = blockIdx.x;
    int f = threadIdx.x;
    int cls = g_cls[row];
    atomicAdd(&g_psum[cls * CC + f], x[(size_t)row * CC + f]);
}

// ---------------- write protoN split (bf16 hi/lo) into image -----------------
DINLINE void write_bimg(int c, int f, float v) {
    unsigned short h, l;
    bsplit(v, h, l);
    int ck = f >> 5, kl = f & 31;
    g_Bimg[((ck * 2 + 0) * 256 + c) * 40 + kl] = h;
    g_Bimg[((ck * 2 + 1) * 256 + c) * 40 + kl] = l;
}

// ---------------- kernel 3: protos + normalized protoN split -----------------
__global__ void pfin_k() {
    int c = blockIdx.x, f = threadIdx.x;
    float v = g_psum[c * CC + f] / (float)g_cntall[c];
    g_protos[c * CC + f] = v;
    float tot = block_reduce_sum(v * v);
    write_bimg(c, f, v * rsqrtf(fmaxf(tot, 1e-12f)));
}

// ---------------- mma.sync bf16x3 GEMM: OUT[n][c] = rnorm[n]*(X[n].pN[c]) ----
__global__ void __launch_bounds__(256, 2)
gemm_mma_k(const float* __restrict__ X, float* __restrict__ OUT,
           int rnoff, int nrows) {
    extern __shared__ char dsm[];
    __shared__ float s_rn[128];
    const float* __restrict__ RN = g_rnorm + rnoff;
    float* __restrict__ O = OUT ? OUT : g_prob;

    const int tid = threadIdx.x, lane = tid & 31, wid = tid >> 5;
    const int wm = wid >> 2, wn = wid & 3;
    const int n0 = blockIdx.x * 128;
    const int c0 = blockIdx.y * 128;

    const uint32_t uA = smem_u32(dsm);
    const uint32_t uAl = uA + 10240;
    const uint32_t uB0 = uA + 20480;
    const uint32_t uB1 = uA + 40960;

    if (tid < 128) {
        int r = n0 + tid;
        s_rn[tid] = (r < nrows) ? RN[r] : 0.f;
    }

    const int a_row = (lane & 7) + 8 * ((lane >> 3) & 1);
    const int a_kb  = 16 * (lane >> 4);
    const int b_row = lane & 7;
    const int b_kb  = 16 * ((lane >> 3) & 1);
    const uint32_t uAh_l = uA  + (uint32_t)((64 * wm + a_row) * 80 + a_kb);
    const uint32_t uAl_l = uAl + (uint32_t)((64 * wm + a_row) * 80 + a_kb);
    const uint32_t bofs  = (uint32_t)((32 * wn + b_row) * 80 + b_kb);

    float acc[4][4][4];
    #pragma unroll
    for (int i = 0; i < 4; i++)
        #pragma unroll
        for (int j = 0; j < 4; j++)
            #pragma unroll
            for (int q = 0; q < 4; q++) acc[i][j][q] = 0.f;

    const int am = tid >> 3, af4 = tid & 7;
    const uint32_t aAst = uA + (uint32_t)(am * 80 + 8 * af4);
    const bool aok[4] = { n0 + am +  0 < nrows, n0 + am + 32 < nrows,
                          n0 + am + 64 < nrows, n0 + am + 96 < nrows };
    const float4 z4 = make_float4(0.f, 0.f, 0.f, 0.f);

    float4 ga[4];
    #pragma unroll
    for (int q = 0; q < 4; q++)
        ga[q] = aok[q] ? *(const float4*)(X + (size_t)(n0 + am + 32 * q) * CC + 4 * af4)
                       : z4;
    {
        const char* src = (const char*)g_Bimg + (size_t)(0 * 2 * 256 + c0) * 80;
        const char* srcL = (const char*)g_Bimg + (size_t)((0 * 2 + 1) * 256 + c0) * 80;
        #pragma unroll
        for (int s = 0; s < 5; s++) {
            int j = tid + 256 * s;
            if (j < 640) cpasync16(uB0 + 16 * j, src + 16 * j);
            else         cpasync16(uB0 + 16 * j, srcL + 16 * (j - 640));
        }
        CP_COMMIT();
    }

    for (int ck = 0; ck < 8; ck++) {
        #pragma unroll
        for (int q = 0; q < 4; q++) {
            uint32_t h0 = bf2pk(ga[q].y, ga[q].x), h1 = bf2pk(ga[q].w, ga[q].z);
            float f0 = __uint_as_float(h0 << 16);
            float f1 = __uint_as_float(h0 & 0xffff0000u);
            float f2 = __uint_as_float(h1 << 16);
            float f3 = __uint_as_float(h1 & 0xffff0000u);
            uint32_t l0 = bf2pk(ga[q].y - f1, ga[q].x - f0);
            uint32_t l1 = bf2pk(ga[q].w - f3, ga[q].z - f2);
            sts_u2(aAst + (uint32_t)(q * 32 * 80), h0, h1);
            sts_u2(aAst + (uint32_t)(q * 32 * 80) + 10240, l0, l1);
        }
        CP_WAIT0();
        __syncthreads();

        if (ck < 7) {
            int kf = (ck + 1) * 32;
            #pragma unroll
            for (int q = 0; q < 4; q++)
                ga[q] = aok[q] ? *(const float4*)(X + (size_t)(n0 + am + 32 * q) * CC
                                                  + kf + 4 * af4)
                               : z4;
            const char* src = (const char*)g_Bimg +
                (size_t)(((ck + 1) * 2 + 0) * 256 + c0) * 80;
            const char* srcL = (const char*)g_Bimg +
                (size_t)(((ck + 1) * 2 + 1) * 256 + c0) * 80;
            uint32_t dst = (ck & 1) ? uB0 : uB1;
            #pragma unroll
            for (int s = 0; s < 5; s++) {
                int j = tid + 256 * s;
                if (j < 640) cpasync16(dst + 16 * j, src + 16 * j);
                else         cpasync16(dst + 16 * j, srcL + 16 * (j - 640));
            }
            CP_COMMIT();
        }

        uint32_t ubh = ((ck & 1) ? uB1 : uB0) + bofs;
        uint32_t ubl = ubh + 10240;
        #pragma unroll
        for (int ks = 0; ks < 2; ks++) {
            uint32_t bh[4][2], bl[4][2];
            #pragma unroll
            for (int nf = 0; nf < 4; nf++) {
                ldm_x2(bh[nf], ubh + nf * 640 + ks * 32);
                ldm_x2(bl[nf], ubl + nf * 640 + ks * 32);
            }
            #pragma unroll
            for (int mf = 0; mf < 4; mf++) {
                uint32_t ah[4], al[4];
                ldm_x4(ah, uAh_l + mf * 1280 + ks * 32);
                ldm_x4(al, uAl_l + mf * 1280 + ks * 32);
                #pragma unroll
                for (int nf = 0; nf < 4; nf++) {
                    mma_bf16(acc[mf][nf], ah, bh[nf]);
                    mma_bf16(acc[mf][nf], al, bh[nf]);
                    mma_bf16(acc[mf][nf], ah, bl[nf]);
                }
            }
        }
        __syncthreads();
    }

    #pragma unroll
    for (int mf = 0; mf < 4; mf++) {
        #pragma unroll
        for (int half = 0; half < 2; half++) {
            int rl = 64 * wm + 16 * mf + (lane >> 2) + 8 * half;
            int grow = n0 + rl;
            if (grow < nrows) {
                float rs = s_rn[rl];
                float* op = O + (size_t)grow * CC + c0 + 32 * wn + 2 * (lane & 3);
                #pragma unroll
                for (int nf = 0; nf < 4; nf++) {
                    float2 v = make_float2(acc[mf][nf][2 * half] * rs,
                                           acc[mf][nf][2 * half + 1] * rs);
                    *(float2*)(op + 8 * nf) = v;
                }
            }
        }
    }
}

// ---------------- kernel: exact per-row top-k -> bf16 split images -----------
__global__ void topk_k() {
    __shared__ float cs[CC];
    for (int i = threadIdx.x; i < CC; i += blockDim.x) cs[i] = 0.f;
    __syncthreads();
    int warp = threadIdx.x >> 5, lane = threadIdx.x & 31;
    for (int row = blockIdx.x * 8 + warp; row < NU; row += gridDim.x * 8) {
        const float* pr = g_prob + (size_t)row * CC;
        float v[8]; unsigned key[8];
        #pragma unroll
        for (int j = 0; j < 8; j++) { v[j] = pr[lane + 32 * j]; key[j] = fkey(v[j]); }
        unsigned T = 0;
        for (int b = 31; b >= 0; b--) {
            unsigned cand = T | (1u << b);
            int cnt = 0;
            #pragma unroll
            for (int j = 0; j < 8; j++) cnt += (key[j] >= cand);
            cnt = (int)__reduce_add_sync(FULLM, (unsigned)cnt);
            if (cnt >= KTOP) T = cand;
        }
        int gt = 0;
        #pragma unroll
        for (int j = 0; j < 8; j++) gt += (key[j] > T);
        gt = (int)__reduce_add_sync(FULLM, (unsigned)gt);
        int r = KTOP - gt;
        int cum = 0;
        #pragma unroll
        for (int j = 0; j < 8; j++) {
            bool eq = (key[j] == T);
            unsigned bal = __ballot_sync(FULLM, eq);
            int pre = cum + __popc(bal & ((1u << lane) - 1u));
            bool keep = (key[j] > T) || (eq && pre < r);
            cum += __popc(bal);
            float o = keep ? v[j] : 0.f;
            unsigned short h, l;
            bsplit(o, h, l);
            size_t idx = (size_t)row * CC + lane + 32 * j;
            g_Ph[idx] = h;
            g_Pl[idx] = l;
            if (o != 0.f) atomicAdd(&cs[lane + 32 * j], o);
        }
    }
    __syncthreads();
    float c = cs[threadIdx.x];
    if (c != 0.f) atomicAdd(&g_colsum[threadIdx.x], c);
}

// ---------------- split-K bf16x3 mma GEMM: S[c][f] += sum_r p[r][c]*x[r][f] --
// Operands are pre-split bf16 gmem images, staged row-major via cp.async and
// loaded as transposed fragments via ldmatrix.trans. Double-buffered.
// Stage layout (per buffer): ph[32][528B] pl[32][528B] xh[32][272B] xl[32][272B]
__global__ void __launch_bounds__(512, 1)
gemm_ptx_mma_k() {
    extern __shared__ char dsm[];
    const uint32_t uS0 = smem_u32(dsm);
    const uint32_t uS1 = uS0 + 51200;

    const int tid = threadIdx.x, lane = tid & 31, wid = tid >> 5;
    const int wm = wid >> 2, wn = wid & 3;    // wm: 64 classes, wn: 32 features
    const int f0 = blockIdx.y * 128;
    const int R0 = blockIdx.x * SEGP;

    // cp.async stage: 3072 16B transfers -> 6 per thread
    auto stage = [&](uint32_t ub, int ck) {
        int r0 = R0 + ck * 32;
        #pragma unroll
        for (int s = 0; s < 6; s++) {
            int t = tid + 512 * s;
            if (t < 2048) {
                int img = t >> 10;                // 0: ph, 1: pl
                int r = (t >> 5) & 31;
                int piece = t & 31;
                const char* src = (const char*)(img ? g_Pl : g_Ph)
                                  + (size_t)(r0 + r) * 512 + piece * 16;
                cpasync16(ub + img * 16896 + r * 528 + piece * 16, src);
            } else {
                int t2 = t - 2048;
                int img = t2 >> 9;                // 0: xh, 1: xl
                int r = (t2 >> 4) & 31;
                int piece = t2 & 15;
                const char* src = (const char*)(img ? g_Xbl : g_Xbh)
                                  + (size_t)(r0 + r) * 512 + f0 * 2 + piece * 16;
                cpasync16(ub + 33792 + img * 8704 + r * 272 + piece * 16, src);
            }
        }
        CP_COMMIT();
    };

    // trans-ldmatrix lane address components
    const int krA = (lane & 7) + 8 * ((lane >> 4) & 1);        // A source row (k)
    const int cmA = 64 * wm + 8 * ((lane >> 3) & 1);           // A column (m)
    const int krB = ((lane & 15) & 7) + 8 * (((lane & 15) >> 3) & 1);  // B row (k)
    const uint32_t aoff = (uint32_t)(krA * 528 + 2 * cmA);
    const uint32_t boff = (uint32_t)(krB * 272 + 2 * (32 * wn));

    float acc[4][4][4];
    #pragma unroll
    for (int i = 0; i < 4; i++)
        #pragma unroll
        for (int j = 0; j < 4; j++)
            #pragma unroll
            for (int q = 0; q < 4; q++) acc[i][j][q] = 0.f;

    stage(uS0, 0);

    for (int ck = 0; ck < CHKP; ck++) {
        if (ck + 1 < CHKP) {
            stage((ck & 1) ? uS0 : uS1, ck + 1);
            CP_WAIT1();
        } else {
            CP_WAIT0();
        }
        __syncthreads();

        uint32_t uP = (ck & 1) ? uS1 : uS0;
        uint32_t uX = uP + 33792;
        #pragma unroll
        for (int ks = 0; ks < 2; ks++) {
            uint32_t bh[4][2], bl[4][2];
            #pragma unroll
            for (int nf = 0; nf < 4; nf++) {
                uint32_t ba = uX + (uint32_t)(ks * 16 * 272) + boff + 2 * (8 * nf);
                ldmT_x2(bh[nf], ba);
                ldmT_x2(bl[nf], ba + 8704);
            }
            #pragma unroll
            for (int mf = 0; mf < 4; mf++) {
                uint32_t aa = uP + (uint32_t)(ks * 16 * 528) + aoff + 2 * (16 * mf);
                uint32_t ah[4], al[4];
                ldmT_x4(ah, aa);
                ldmT_x4(al, aa + 16896);
                #pragma unroll
                for (int nf = 0; nf < 4; nf++) {
                    mma_bf16(acc[mf][nf], ah, bh[nf]);
                    mma_bf16(acc[mf][nf], al, bh[nf]);
                    mma_bf16(acc[mf][nf], ah, bl[nf]);
                }
            }
        }
        __syncthreads();
    }

    // epilogue: atomic accumulate into g_S
    #pragma unroll
    for (int mf = 0; mf < 4; mf++) {
        #pragma unroll
        for (int nf = 0; nf < 4; nf++) {
            #pragma unroll
            for (int half = 0; half < 2; half++) {
                int c = 64 * wm + 16 * mf + (lane >> 2) + 8 * half;
                int f = f0 + 32 * wn + 8 * nf + 2 * (lane & 3);
                atomicAdd(&g_S[c * CC + f + 0], acc[mf][nf][2 * half + 0]);
                atomicAdd(&g_S[c * CC + f + 1], acc[mf][nf][2 * half + 1]);
            }
        }
    }
}

// ---------------- kernel: proto update + renorm + split write ----------------
__global__ void pfin2_k() {
    int c = blockIdx.x, f = threadIdx.x;
    float cp = g_colsum[c];
    float denom = cp + (float)g_cntlab[c];
    float pv = g_protos[c * CC + f];
    float nv = pv + g_S[c * CC + f] / denom - (cp / denom) * pv;
    float tot = block_reduce_sum(nv * nv);
    write_bimg(c, f, nv * rsqrtf(fmaxf(tot, 1e-12f)));
}

// ---------------- launch ------------------------------------------------------
extern "C" void kernel_launch(void* const* d_in, const int* in_sizes, int n_in,
                              void* d_out, int out_size) {
    (void)in_sizes; (void)n_in; (void)out_size;
    const float* x = (const float*)d_in[0];
    const float* labels = (const float*)d_in[1];
    float* out = (float*)d_out;

    cudaFuncSetAttribute(gemm_mma_k, cudaFuncAttributeMaxDynamicSharedMemorySize,
                         SMEM_MMA);
    cudaFuncSetAttribute(gemm_ptx_mma_k,
                         cudaFuncAttributeMaxDynamicSharedMemorySize, SMEM_PTX);

    zero_k<<<CC, 256>>>();
    prep_k<<<1480, 256>>>(x, labels);
    paccum_k<<<LL, 256>>>(x);
    pfin_k<<<CC, 256>>>();
    gemm_mma_k<<<dim3((NU + 127) / 128, 2), 256, SMEM_MMA>>>(
        x + (size_t)LL * CC, nullptr, LL, NU);
    topk_k<<<1563, 256>>>();
    gemm_ptx_mma_k<<<dim3(NSEGP, 2), 512, SMEM_PTX>>>();
    pfin2_k<<<CC, 256>>>();
    gemm_mma_k<<<dim3((NN + 127) / 128, 2), 256, SMEM_MMA>>>(x, out, 0, NN);
}